// round 3
// baseline (speedup 1.0000x reference)
#include <cuda_runtime.h>

// EdgeModel fused kernel (round 2: edge_index is INT32 — JAX x64-disabled
// silently downcasts the reference's "int64" randint to int32).
//
// Per block: 64 edges, 512 threads.
//   Phase G: gather A tile (64 x 384) = [h[row] | h[col] | radial*128] into smem.
//   Phase 1: x1 = silu(A @ W1 + b1)   (K=384, tiled by 32)
//   Phase 2: out = silu(x1 @ W2 + b2) (K=128, tiled by 32)

#define BE 64
#define THREADS 512
#define KT 32
#define AS_STRIDE 388   // 384 + 4 pad: conflict-free column reads, float4-aligned rows
#define XS_STRIDE 132   // 128 + 4 pad

__device__ __forceinline__ float silu_f(float x) {
    return x / (1.0f + __expf(-x));
}

extern "C" __global__ void __launch_bounds__(THREADS, 1)
edge_model_kernel(const int* __restrict__ edge_index,        // (2, E) int32
                  const float* __restrict__ h,               // (N, 128)
                  const float* __restrict__ coord,           // (N, 3)
                  const float* __restrict__ W1,              // (384, 128)
                  const float* __restrict__ b1,              // (128)
                  const float* __restrict__ W2,              // (128, 128)
                  const float* __restrict__ b2,              // (128)
                  float* __restrict__ out,                   // (E, 128)
                  int E)
{
    extern __shared__ float smem[];
    float* As = smem;                          // 64 x 388
    float* Ws = As + BE * AS_STRIDE;           // 32 x 128
    float* Xs = Ws + KT * 128;                 // 64 x 132

    const int t  = threadIdx.x;
    const int tx = t & 31;        // lane: owns output columns [tx*4, tx*4+4)
    const int ty = t >> 5;        // warp id 0..15: owns edges [ty*4, ty*4+4) in compute

    const long long e0 = (long long)blockIdx.x * BE;

    // ---------------- Phase G: gather A tile ----------------
    // warp w fills edges w, w+16, w+32, w+48 (one full 384-float row per edge)
    #pragma unroll
    for (int i = 0; i < 4; i++) {
        const int e = ty + 16 * i;
        long long eg = e0 + e;
        if (eg >= E) eg = (long long)E - 1;   // clamp; garbage rows never stored
        const int row = edge_index[eg];
        const int col = edge_index[(long long)E + eg];

        float4 s4 = *(const float4*)(h + (size_t)row * 128 + tx * 4);
        float4 t4 = *(const float4*)(h + (size_t)col * 128 + tx * 4);
        *(float4*)(As + e * AS_STRIDE +       tx * 4) = s4;
        *(float4*)(As + e * AS_STRIDE + 128 + tx * 4) = t4;

        const float dx = coord[(size_t)row * 3 + 0] - coord[(size_t)col * 3 + 0];
        const float dy = coord[(size_t)row * 3 + 1] - coord[(size_t)col * 3 + 1];
        const float dz = coord[(size_t)row * 3 + 2] - coord[(size_t)col * 3 + 2];
        const float r  = dx * dx + dy * dy + dz * dz;
        *(float4*)(As + e * AS_STRIDE + 256 + tx * 4) = make_float4(r, r, r, r);
    }
    __syncthreads();

    // ---------------- Phase 1: x1 = silu(A @ W1 + b1) ----------------
    float acc[4][4];
    #pragma unroll
    for (int i = 0; i < 4; i++)
        #pragma unroll
        for (int j = 0; j < 4; j++) acc[i][j] = 0.0f;

    #pragma unroll 1
    for (int kt = 0; kt < 384 / KT; kt++) {
        // stage W1 K-tile: 32 x 128 floats, 512 threads -> 2 float4 each
        #pragma unroll
        for (int l = 0; l < 2; l++) {
            const int idx = t + l * THREADS;        // float4 index 0..1023
            const int kr  = idx >> 5;               // row within tile (32 float4/row)
            const int jc  = (idx & 31) * 4;
            *(float4*)(Ws + kr * 128 + jc) =
                *(const float4*)(W1 + (size_t)(kt * KT + kr) * 128 + jc);
        }
        __syncthreads();

        const float* Arow = As + (ty * 4) * AS_STRIDE + kt * KT;
        #pragma unroll
        for (int k = 0; k < KT; k++) {
            const float4 w4 = *(const float4*)(Ws + k * 128 + tx * 4);
            float a0 = Arow[0 * AS_STRIDE + k];
            float a1 = Arow[1 * AS_STRIDE + k];
            float a2 = Arow[2 * AS_STRIDE + k];
            float a3 = Arow[3 * AS_STRIDE + k];
            acc[0][0] += a0 * w4.x; acc[0][1] += a0 * w4.y;
            acc[0][2] += a0 * w4.z; acc[0][3] += a0 * w4.w;
            acc[1][0] += a1 * w4.x; acc[1][1] += a1 * w4.y;
            acc[1][2] += a1 * w4.z; acc[1][3] += a1 * w4.w;
            acc[2][0] += a2 * w4.x; acc[2][1] += a2 * w4.y;
            acc[2][2] += a2 * w4.z; acc[2][3] += a2 * w4.w;
            acc[3][0] += a3 * w4.x; acc[3][1] += a3 * w4.y;
            acc[3][2] += a3 * w4.z; acc[3][3] += a3 * w4.w;
        }
        __syncthreads();
    }

    // bias + silu -> Xs
    {
        const float4 bb1 = *(const float4*)(b1 + tx * 4);
        #pragma unroll
        for (int i = 0; i < 4; i++) {
            float4 v;
            v.x = silu_f(acc[i][0] + bb1.x);
            v.y = silu_f(acc[i][1] + bb1.y);
            v.z = silu_f(acc[i][2] + bb1.z);
            v.w = silu_f(acc[i][3] + bb1.w);
            *(float4*)(Xs + (ty * 4 + i) * XS_STRIDE + tx * 4) = v;
        }
    }
    __syncthreads();

    // ---------------- Phase 2: out = silu(x1 @ W2 + b2) ----------------
    #pragma unroll
    for (int i = 0; i < 4; i++)
        #pragma unroll
        for (int j = 0; j < 4; j++) acc[i][j] = 0.0f;

    #pragma unroll 1
    for (int kt = 0; kt < 128 / KT; kt++) {
        #pragma unroll
        for (int l = 0; l < 2; l++) {
            const int idx = t + l * THREADS;
            const int kr  = idx >> 5;
            const int jc  = (idx & 31) * 4;
            *(float4*)(Ws + kr * 128 + jc) =
                *(const float4*)(W2 + (size_t)(kt * KT + kr) * 128 + jc);
        }
        __syncthreads();

        const float* Xrow = Xs + (ty * 4) * XS_STRIDE + kt * KT;
        #pragma unroll
        for (int k = 0; k < KT; k++) {
            const float4 w4 = *(const float4*)(Ws + k * 128 + tx * 4);
            float a0 = Xrow[0 * XS_STRIDE + k];
            float a1 = Xrow[1 * XS_STRIDE + k];
            float a2 = Xrow[2 * XS_STRIDE + k];
            float a3 = Xrow[3 * XS_STRIDE + k];
            acc[0][0] += a0 * w4.x; acc[0][1] += a0 * w4.y;
            acc[0][2] += a0 * w4.z; acc[0][3] += a0 * w4.w;
            acc[1][0] += a1 * w4.x; acc[1][1] += a1 * w4.y;
            acc[1][2] += a1 * w4.z; acc[1][3] += a1 * w4.w;
            acc[2][0] += a2 * w4.x; acc[2][1] += a2 * w4.y;
            acc[2][2] += a2 * w4.z; acc[2][3] += a2 * w4.w;
            acc[3][0] += a3 * w4.x; acc[3][1] += a3 * w4.y;
            acc[3][2] += a3 * w4.z; acc[3][3] += a3 * w4.w;
        }
        __syncthreads();
    }

    // bias + silu -> gmem (coalesced float4 per row)
    {
        const float4 bb2 = *(const float4*)(b2 + tx * 4);
        #pragma unroll
        for (int i = 0; i < 4; i++) {
            const long long eg = e0 + ty * 4 + i;
            if (eg < E) {
                float4 v;
                v.x = silu_f(acc[i][0] + bb2.x);
                v.y = silu_f(acc[i][1] + bb2.y);
                v.z = silu_f(acc[i][2] + bb2.z);
                v.w = silu_f(acc[i][3] + bb2.w);
                *(float4*)(out + eg * 128 + tx * 4) = v;
            }
        }
    }
}

extern "C" void kernel_launch(void* const* d_in, const int* in_sizes, int n_in,
                              void* d_out, int out_size)
{
    const int*   edge_index = (const int*)d_in[0];     // (2,E) int32 (JAX x64 off)
    const float* h          = (const float*)d_in[1];   // (N,128)
    const float* coord      = (const float*)d_in[2];   // (N,3)
    // d_in[3] = edge_attr (E,1): unused by the reference computation
    const float* W1         = (const float*)d_in[4];   // (384,128)
    const float* b1         = (const float*)d_in[5];   // (128)
    const float* W2         = (const float*)d_in[6];   // (128,128)
    const float* b2         = (const float*)d_in[7];   // (128)
    float*       out        = (float*)d_out;           // (E,128)

    const int E = in_sizes[3];  // edge_attr element count == E
    const int blocks = (E + BE - 1) / BE;

    const size_t smem_bytes =
        (size_t)(BE * AS_STRIDE + KT * 128 + BE * XS_STRIDE) * sizeof(float);

    cudaFuncSetAttribute(edge_model_kernel,
                         cudaFuncAttributeMaxDynamicSharedMemorySize,
                         (int)smem_bytes);

    edge_model_kernel<<<blocks, THREADS, smem_bytes>>>(
        edge_index, h, coord, W1, b1, W2, b2, out, E);
}

// round 6
// speedup vs baseline: 3.1722x; 3.1722x over previous
#include <cuda_runtime.h>
#include <cuda_bf16.h>
#include <cstdint>

// ===== round 6: mma.sync bf16 split-precision fused EdgeModel (no tcgen05 —
// harness compiles compute_100 PTX, which rejects all sm_100a features) =====
//
// k0: pack W1T/W2T as bf16 hi/lo chunk-major [chunk][n][k64]; colsum W1[256:].
// k1: per CTA 128 edges, 256 threads (8 warps, 4x2 warp grid, 32x64 warp tile):
//   GEMM1: D1 = [h[row]|h[col]] (128x256) @ W1T^T, 4 K-chunks of 64,
//          3-term bf16 split (hh + hl + lh), mma.sync.m16n8k16.
//   epi1 : x1 = silu(D1 + r*w1r + b1) -> bf16 hi/lo [m][136] in smem.
//   GEMM2: D2 = x1 @ W2T^T (K=128, 2 chunks). epi2: out = silu(D2 + b2).

__device__ __nv_bfloat16 g_W1H[4 * 128 * 64];
__device__ __nv_bfloat16 g_W1L[4 * 128 * 64];
__device__ __nv_bfloat16 g_W2H[2 * 128 * 64];
__device__ __nv_bfloat16 g_W2L[2 * 128 * 64];
__device__ float g_w1r[128];

#define BE 128
#define THREADS 256

// A/B chunk tiles: [128][72] bf16 (144B row stride = 9*16B -> ldmatrix conflict-free)
// X1 tiles:        [128][136] bf16 (272B = 17*16B)
#define AST 72
#define XST 136

// smem byte offsets
#define SM_ROW  0
#define SM_COL  512
#define SM_RR   1024
#define SM_W1R  1536
#define SM_B1   2048
#define SM_B2   2560
#define SM_X1H  3072                    // 128*272 = 34816
#define SM_X1L  (SM_X1H + 34816)        // 34816
#define SM_AH   SM_X1H                  // alias: A chunk hi (18432)
#define SM_AL   (SM_X1H + 18432)        // alias: A chunk lo (18432)
#define SM_BH   (SM_X1L + 34816)        // 18432
#define SM_BL   (SM_BH + 18432)         // 18432
#define SMEM_TOTAL (SM_BL + 18432)      // 109568

__device__ __forceinline__ uint32_t smem_to_u32(const void* p) {
    uint32_t a;
    asm("{ .reg .u64 t; cvta.to.shared.u64 t, %1; cvt.u32.u64 %0, t; }" : "=r"(a) : "l"(p));
    return a;
}
__device__ __forceinline__ void ldsm_x4(uint32_t addr, uint32_t* r) {
    asm volatile("ldmatrix.sync.aligned.m8n8.x4.shared.b16 {%0,%1,%2,%3}, [%4];"
                 : "=r"(r[0]), "=r"(r[1]), "=r"(r[2]), "=r"(r[3]) : "r"(addr));
}
__device__ __forceinline__ void mma_bf16(float* d, const uint32_t* a, uint32_t b0, uint32_t b1) {
    asm volatile("mma.sync.aligned.m16n8k16.row.col.f32.bf16.bf16.f32 "
                 "{%0,%1,%2,%3}, {%4,%5,%6,%7}, {%8,%9}, {%0,%1,%2,%3};"
                 : "+f"(d[0]), "+f"(d[1]), "+f"(d[2]), "+f"(d[3])
                 : "r"(a[0]), "r"(a[1]), "r"(a[2]), "r"(a[3]), "r"(b0), "r"(b1));
}
__device__ __forceinline__ float silu_f(float x) { return x / (1.0f + __expf(-x)); }

// split fp32 float4 into bf16 hi/lo 8-byte packets
__device__ __forceinline__ void split4(float4 v, uint2& hw, uint2& lw) {
    __nv_bfloat162 h01 = __floats2bfloat162_rn(v.x, v.y);
    __nv_bfloat162 h23 = __floats2bfloat162_rn(v.z, v.w);
    __nv_bfloat162 l01 = __floats2bfloat162_rn(v.x - __low2float(h01), v.y - __high2float(h01));
    __nv_bfloat162 l23 = __floats2bfloat162_rn(v.z - __low2float(h23), v.w - __high2float(h23));
    memcpy(&hw.x, &h01, 4); memcpy(&hw.y, &h23, 4);
    memcpy(&lw.x, &l01, 4); memcpy(&lw.y, &l23, 4);
}
__device__ __forceinline__ uint32_t pack_bf16x2(float a, float b) {
    __nv_bfloat162 p = __floats2bfloat162_rn(a, b);
    uint32_t u; memcpy(&u, &p, 4); return u;
}

// ---------- k0: pack weights ----------
extern "C" __global__ void pack_weights_kernel(const float* __restrict__ W1,
                                               const float* __restrict__ W2)
{
    int idx = blockIdx.x * 256 + threadIdx.x;
    if (idx < 32768) {                    // W1T: [c][n][kk], c<4
        int c = idx >> 13, r = idx & 8191;
        int n = r >> 6, kk = r & 63;
        float a = W1[(size_t)(c * 64 + kk) * 128 + n];
        __nv_bfloat16 hi = __float2bfloat16(a);
        g_W1H[idx] = hi;
        g_W1L[idx] = __float2bfloat16(a - __bfloat162float(hi));
    } else if (idx < 49152) {             // W2T: [c][n][kk], c<2
        int j = idx - 32768;
        int c = j >> 13, r = j & 8191;
        int n = r >> 6, kk = r & 63;
        float a = W2[(size_t)(c * 64 + kk) * 128 + n];
        __nv_bfloat16 hi = __float2bfloat16(a);
        g_W2H[j] = hi;
        g_W2L[j] = __float2bfloat16(a - __bfloat162float(hi));
    } else if (idx < 49280) {             // radial colsum of W1 rows 256..383
        int n = idx - 49152;
        float s = 0.0f;
        for (int k = 0; k < 128; k++) s += W1[(size_t)(256 + k) * 128 + n];
        g_w1r[n] = s;
    }
}

// ---------- k1: fused edge model ----------
extern "C" __global__ void __launch_bounds__(THREADS, 2)
edge_model_mma_kernel(const int* __restrict__ edge_index,
                      const float* __restrict__ h,
                      const float* __restrict__ coord,
                      const float* __restrict__ b1,
                      const float* __restrict__ b2,
                      float* __restrict__ out,
                      int E)
{
    extern __shared__ char smem[];
    const uint32_t sb = smem_to_u32(smem);
    const int t = threadIdx.x;
    const int wid = t >> 5, lane = t & 31;
    const int wr = wid >> 1, wc = wid & 1;       // warp grid 4(m) x 2(n)
    const long long e0 = (long long)blockIdx.x * BE;

    int* rowi = (int*)(smem + SM_ROW);
    int* coli = (int*)(smem + SM_COL);
    float* rr  = (float*)(smem + SM_RR);
    float* w1r = (float*)(smem + SM_W1R);
    float* b1s = (float*)(smem + SM_B1);
    float* b2s = (float*)(smem + SM_B2);

    if (t < BE) {
        long long eg = e0 + t;
        if (eg >= E) eg = (long long)E - 1;
        int r = edge_index[eg];
        int c = edge_index[(long long)E + eg];
        rowi[t] = r; coli[t] = c;
        float dx = coord[(size_t)r * 3 + 0] - coord[(size_t)c * 3 + 0];
        float dy = coord[(size_t)r * 3 + 1] - coord[(size_t)c * 3 + 1];
        float dz = coord[(size_t)r * 3 + 2] - coord[(size_t)c * 3 + 2];
        rr[t]  = dx * dx + dy * dy + dz * dz;
        w1r[t] = g_w1r[t];
        b1s[t] = b1[t];
        b2s[t] = b2[t];
    }
    __syncthreads();

    float acc[2][8][4];
    #pragma unroll
    for (int i = 0; i < 2; i++)
        #pragma unroll
        for (int j = 0; j < 8; j++)
            #pragma unroll
            for (int q = 0; q < 4; q++) acc[i][j][q] = 0.0f;

    // ldmatrix lane-address components (constant per thread)
    const int lm_m = lane & 15;                 // A: row within 16
    const int lm_k = (lane >> 4) * 8;           // A: k half
    const int lb_n = ((lane >> 4) << 3) + (lane & 7);  // B: n within 16
    const int lb_k = ((lane >> 3) & 1) * 8;     // B: k half

    // ---------------- GEMM1: 4 K-chunks of 64 ----------------
    #pragma unroll 1
    for (int c = 0; c < 4; c++) {
        // stage A chunk: gather + split
        #pragma unroll
        for (int j = 0; j < 8; j++) {
            int i = t + j * THREADS;            // 0..2047
            int m = i >> 4, q = i & 15;
            const float* hp = (c < 2) ? h + (size_t)rowi[m] * 128 + c * 64
                                      : h + (size_t)coli[m] * 128 + (c - 2) * 64;
            float4 v = *(const float4*)(hp + q * 4);
            uint2 hw, lw; split4(v, hw, lw);
            *(uint2*)(smem + SM_AH + m * (AST * 2) + q * 8) = hw;
            *(uint2*)(smem + SM_AL + m * (AST * 2) + q * 8) = lw;
        }
        // stage B chunk (straight copy, 1024 x 16B per buffer)
        #pragma unroll
        for (int j = 0; j < 4; j++) {
            int i = t + j * THREADS;            // 0..1023
            int rw = i >> 3, seg = i & 7;
            *(uint4*)(smem + SM_BH + rw * (AST * 2) + seg * 16) =
                *(const uint4*)(g_W1H + (size_t)c * 8192 + rw * 64 + seg * 8);
            *(uint4*)(smem + SM_BL + rw * (AST * 2) + seg * 16) =
                *(const uint4*)(g_W1L + (size_t)c * 8192 + rw * 64 + seg * 8);
        }
        __syncthreads();

        #pragma unroll
        for (int ks = 0; ks < 4; ks++) {
            const int k0 = ks * 16;
            uint32_t ah[2][4], al[2][4];
            #pragma unroll
            for (int mt = 0; mt < 2; mt++) {
                uint32_t off = (uint32_t)((wr * 32 + mt * 16 + lm_m) * (AST * 2) + (k0 + lm_k) * 2);
                ldsm_x4(sb + SM_AH + off, ah[mt]);
                ldsm_x4(sb + SM_AL + off, al[mt]);
            }
            #pragma unroll
            for (int nt2 = 0; nt2 < 4; nt2++) {
                uint32_t boff = (uint32_t)((wc * 64 + nt2 * 16 + lb_n) * (AST * 2) + (k0 + lb_k) * 2);
                uint32_t bh[4], bl[4];
                ldsm_x4(sb + SM_BH + boff, bh);
                ldsm_x4(sb + SM_BL + boff, bl);
                #pragma unroll
                for (int mt = 0; mt < 2; mt++) {
                    mma_bf16(acc[mt][2 * nt2],     ah[mt], bh[0], bh[1]);
                    mma_bf16(acc[mt][2 * nt2],     ah[mt], bl[0], bl[1]);
                    mma_bf16(acc[mt][2 * nt2],     al[mt], bh[0], bh[1]);
                    mma_bf16(acc[mt][2 * nt2 + 1], ah[mt], bh[2], bh[3]);
                    mma_bf16(acc[mt][2 * nt2 + 1], ah[mt], bl[2], bl[3]);
                    mma_bf16(acc[mt][2 * nt2 + 1], al[mt], bh[2], bh[3]);
                }
            }
        }
        __syncthreads();
    }

    // ---------------- epilogue 1: x1 = silu(D1 + r*w1r + b1) ----------------
    {
        #pragma unroll
        for (int mt = 0; mt < 2; mt++) {
            const int m = wr * 32 + mt * 16 + (lane >> 2);
            const float r0 = rr[m], r1 = rr[m + 8];
            #pragma unroll
            for (int nt = 0; nt < 8; nt++) {
                const int n = wc * 64 + nt * 8 + 2 * (lane & 3);
                const float wa = w1r[n], wb = w1r[n + 1];
                const float ba = b1s[n], bb = b1s[n + 1];
                float v0 = silu_f(acc[mt][nt][0] + r0 * wa + ba);
                float v1 = silu_f(acc[mt][nt][1] + r0 * wb + bb);
                float v2 = silu_f(acc[mt][nt][2] + r1 * wa + ba);
                float v3 = silu_f(acc[mt][nt][3] + r1 * wb + bb);
                __nv_bfloat16 h0 = __float2bfloat16(v0), h1 = __float2bfloat16(v1);
                __nv_bfloat16 h2 = __float2bfloat16(v2), h3 = __float2bfloat16(v3);
                uint32_t hw01, hw23, lw01, lw23;
                { __nv_bfloat162 p = __nv_bfloat162(h0, h1); memcpy(&hw01, &p, 4); }
                { __nv_bfloat162 p = __nv_bfloat162(h2, h3); memcpy(&hw23, &p, 4); }
                lw01 = pack_bf16x2(v0 - __bfloat162float(h0), v1 - __bfloat162float(h1));
                lw23 = pack_bf16x2(v2 - __bfloat162float(h2), v3 - __bfloat162float(h3));
                *(uint32_t*)(smem + SM_X1H + m * (XST * 2) + n * 2) = hw01;
                *(uint32_t*)(smem + SM_X1H + (m + 8) * (XST * 2) + n * 2) = hw23;
                *(uint32_t*)(smem + SM_X1L + m * (XST * 2) + n * 2) = lw01;
                *(uint32_t*)(smem + SM_X1L + (m + 8) * (XST * 2) + n * 2) = lw23;
            }
        }
    }
    __syncthreads();

    // zero accumulators for GEMM2
    #pragma unroll
    for (int i = 0; i < 2; i++)
        #pragma unroll
        for (int j = 0; j < 8; j++)
            #pragma unroll
            for (int q = 0; q < 4; q++) acc[i][j][q] = 0.0f;

    // ---------------- GEMM2: 2 K-chunks of 64 ----------------
    #pragma unroll 1
    for (int kc = 0; kc < 2; kc++) {
        #pragma unroll
        for (int j = 0; j < 4; j++) {
            int i = t + j * THREADS;
            int rw = i >> 3, seg = i & 7;
            *(uint4*)(smem + SM_BH + rw * (AST * 2) + seg * 16) =
                *(const uint4*)(g_W2H + (size_t)kc * 8192 + rw * 64 + seg * 8);
            *(uint4*)(smem + SM_BL + rw * (AST * 2) + seg * 16) =
                *(const uint4*)(g_W2L + (size_t)kc * 8192 + rw * 64 + seg * 8);
        }
        __syncthreads();

        #pragma unroll
        for (int ks = 0; ks < 4; ks++) {
            const int k0 = ks * 16;
            uint32_t ah[2][4], al[2][4];
            #pragma unroll
            for (int mt = 0; mt < 2; mt++) {
                uint32_t off = (uint32_t)((wr * 32 + mt * 16 + lm_m) * (XST * 2) +
                                          (kc * 64 + k0 + lm_k) * 2);
                ldsm_x4(sb + SM_X1H + off, ah[mt]);
                ldsm_x4(sb + SM_X1L + off, al[mt]);
            }
            #pragma unroll
            for (int nt2 = 0; nt2 < 4; nt2++) {
                uint32_t boff = (uint32_t)((wc * 64 + nt2 * 16 + lb_n) * (AST * 2) + (k0 + lb_k) * 2);
                uint32_t bh[4], bl[4];
                ldsm_x4(sb + SM_BH + boff, bh);
                ldsm_x4(sb + SM_BL + boff, bl);
                #pragma unroll
                for (int mt = 0; mt < 2; mt++) {
                    mma_bf16(acc[mt][2 * nt2],     ah[mt], bh[0], bh[1]);
                    mma_bf16(acc[mt][2 * nt2],     ah[mt], bl[0], bl[1]);
                    mma_bf16(acc[mt][2 * nt2],     al[mt], bh[0], bh[1]);
                    mma_bf16(acc[mt][2 * nt2 + 1], ah[mt], bh[2], bh[3]);
                    mma_bf16(acc[mt][2 * nt2 + 1], ah[mt], bl[2], bl[3]);
                    mma_bf16(acc[mt][2 * nt2 + 1], al[mt], bh[2], bh[3]);
                }
            }
        }
        __syncthreads();
    }

    // ---------------- epilogue 2: out = silu(D2 + b2) ----------------
    {
        #pragma unroll
        for (int mt = 0; mt < 2; mt++) {
            const int m = wr * 32 + mt * 16 + (lane >> 2);
            const long long eg0 = e0 + m, eg1 = e0 + m + 8;
            #pragma unroll
            for (int nt = 0; nt < 8; nt++) {
                const int n = wc * 64 + nt * 8 + 2 * (lane & 3);
                const float ba = b2s[n], bb = b2s[n + 1];
                if (eg0 < E) {
                    float2 v = make_float2(silu_f(acc[mt][nt][0] + ba),
                                           silu_f(acc[mt][nt][1] + bb));
                    *(float2*)(out + (size_t)eg0 * 128 + n) = v;
                }
                if (eg1 < E) {
                    float2 v = make_float2(silu_f(acc[mt][nt][2] + ba),
                                           silu_f(acc[mt][nt][3] + bb));
                    *(float2*)(out + (size_t)eg1 * 128 + n) = v;
                }
            }
        }
    }
}

extern "C" void kernel_launch(void* const* d_in, const int* in_sizes, int n_in,
                              void* d_out, int out_size)
{
    const int*   edge_index = (const int*)d_in[0];
    const float* h          = (const float*)d_in[1];
    const float* coord      = (const float*)d_in[2];
    const float* W1         = (const float*)d_in[4];
    const float* b1         = (const float*)d_in[5];
    const float* W2         = (const float*)d_in[6];
    const float* b2         = (const float*)d_in[7];
    float*       out        = (float*)d_out;

    const int E = in_sizes[3];

    pack_weights_kernel<<<193, 256>>>(W1, W2);

    cudaFuncSetAttribute(edge_model_mma_kernel,
                         cudaFuncAttributeMaxDynamicSharedMemorySize, SMEM_TOTAL);
    const int blocks = (E + BE - 1) / BE;
    edge_model_mma_kernel<<<blocks, THREADS, SMEM_TOTAL>>>(
        edge_index, h, coord, b1, b2, out, E);
}